// round 1
// baseline (speedup 1.0000x reference)
#include <cuda_runtime.h>
#include <math.h>

// ---------------- problem constants ----------------
#define Bn      64
#define Hh      56
#define Wd      56
#define Cc      96
#define NHEADS  3
#define WIN     7
#define NN      49            // tokens per window
#define NWn     64            // windows per image
#define BW      (Bn*NWn)      // 4096 total windows
#define Dd      32            // head dim
#define HID     384
#define TOKENS  (Bn*Hh*Wd)    // 200704

// ---------------- device scratch (no allocation allowed) ----------------
__device__ float g_qkv[(size_t)BW * 9 * NN * Dd];   // [win][which(3)][head(3)][n][d]  ~231 MB
__device__ float g_partial[2 * BW];                 // per-block sumsq q / k
__device__ float g_bias[NHEADS * NN * NN];          // CPB bias table
__device__ float g_scale;                           // 1/(|q||k| max(tau,.01))

__device__ __forceinline__ float gelu_tanh(float x) {
    float x3 = x * x * x;
    return 0.5f * x * (1.0f + tanhf(0.7978845608028654f * (x + 0.044715f * x3)));
}

// ---------------- kernel 1: CPB bias table ----------------
__global__ void kprep(const float* __restrict__ w1, const float* __restrict__ b1,
                      const float* __restrict__ w2, const float* __restrict__ b2) {
    int t = threadIdx.x;
    for (int idx = t; idx < NN * NN; idx += blockDim.x) {
        int n = idx / NN, m = idx - NN * n;
        float di = (float)(n / WIN - m / WIN);
        float dj = (float)(n % WIN - m % WIN);
        float fdi = (di > 0.f ? 1.f : (di < 0.f ? -1.f : 0.f)) * log1pf(fabsf(di));
        float fdj = (dj > 0.f ? 1.f : (dj < 0.f ? -1.f : 0.f)) * log1pf(fabsf(dj));
        float a0 = 0.f, a1 = 0.f, a2 = 0.f;
        for (int h = 0; h < 128; h++) {
            float v = fdi * w1[h] + fdj * w1[128 + h] + b1[h];
            float g = gelu_tanh(v);
            a0 += g * w2[h * 3 + 0];
            a1 += g * w2[h * 3 + 1];
            a2 += g * w2[h * 3 + 2];
        }
        g_bias[0 * 2401 + idx] = a0 + b2[0];
        g_bias[1 * 2401 + idx] = a1 + b2[1];
        g_bias[2 * 2401 + idx] = a2 + b2[2];
    }
}

// ---------------- kernel 2: LN + shift/window gather + QKV GEMM + sumsq ----------------
#define SMEM_QKV_FLOATS (96*288 + 49*97 + 288 + 49 + 49)
__global__ void __launch_bounds__(288) kqkv(const float* __restrict__ x,
                                            const float* __restrict__ n1g, const float* __restrict__ n1b,
                                            const float* __restrict__ qw,  const float* __restrict__ qb) {
    extern __shared__ float sm[];
    float* w_s  = sm;                 // 27648
    float* h_s  = w_s + 96 * 288;     // 49*97 padded
    float* b_s  = h_s + 49 * 97;      // 288
    float* mu_s = b_s + 288;          // 49
    float* rs_s = mu_s + 49;          // 49
    __shared__ float redq[9], redk[9];

    int t = threadIdx.x;
    int bid = blockIdx.x;
    int b = bid >> 6, wi = bid & 63, wh = wi >> 3, ww = wi & 7;

    for (int i = t; i < 96 * 288; i += 288) w_s[i] = qw[i];
    b_s[t] = qb[t];

    // gather window tokens through cyclic shift
    for (int idx = t; idx < NN * Cc; idx += 288) {
        int n = idx / 96, c = idx - 96 * n;
        int i = n / 7, j = n - 7 * i;
        int hs = wh * 7 + i + 3; if (hs >= 56) hs -= 56;
        int ws = ww * 7 + j + 3; if (ws >= 56) ws -= 56;
        h_s[n * 97 + c] = x[((size_t)b * 3136 + hs * 56 + ws) * 96 + c];
    }
    __syncthreads();
    if (t < 49) {
        float s = 0.f, ss = 0.f;
        for (int k = 0; k < 96; k++) { float v = h_s[t * 97 + k]; s += v; ss += v * v; }
        float mu = s * (1.f / 96.f);
        float var = ss * (1.f / 96.f) - mu * mu;
        mu_s[t] = mu; rs_s[t] = rsqrtf(var + 1e-5f);
    }
    __syncthreads();
    for (int idx = t; idx < NN * Cc; idx += 288) {
        int n = idx / 96, c = idx - 96 * n;
        h_s[n * 97 + c] = (h_s[n * 97 + c] - mu_s[n]) * rs_s[n] * n1g[c] + n1b[c];
    }
    __syncthreads();

    // each thread owns one of 288 output columns; 7-row register blocking
    int o = t;
    int which = o / 96, col = o - 96 * which, head = col >> 5, dd = col & 31;
    float bo = b_s[o];
    float* outp = g_qkv + ((size_t)bid * 9 + which * 3 + head) * (NN * Dd) + dd;
    float sqq = 0.f, sqk = 0.f;
    for (int g = 0; g < 7; g++) {
        float acc[7] = {0.f, 0.f, 0.f, 0.f, 0.f, 0.f, 0.f};
        const float* hrow = h_s + g * 7 * 97;
        for (int k = 0; k < 96; k++) {
            float w = w_s[k * 288 + o];
#pragma unroll
            for (int r = 0; r < 7; r++) acc[r] += hrow[r * 97 + k] * w;
        }
#pragma unroll
        for (int r = 0; r < 7; r++) {
            int n = g * 7 + r;
            float v = acc[r] + bo;
            outp[n * 32] = v;
            if (which == 0) sqq += v * v; else if (which == 1) sqk += v * v;
        }
    }
    // deterministic block reduction of sumsq
    for (int off = 16; off; off >>= 1) {
        sqq += __shfl_down_sync(0xffffffffu, sqq, off);
        sqk += __shfl_down_sync(0xffffffffu, sqk, off);
    }
    int wid = t >> 5, lane = t & 31;
    if (lane == 0) { redq[wid] = sqq; redk[wid] = sqk; }
    __syncthreads();
    if (t == 0) {
        float a = 0.f, bb = 0.f;
        for (int i = 0; i < 9; i++) { a += redq[i]; bb += redk[i]; }
        g_partial[bid] = a; g_partial[BW + bid] = bb;
    }
}

// ---------------- kernel 3: deterministic global reduce -> scale ----------------
__global__ void kreduce(const float* __restrict__ tau) {
    __shared__ float sq[1024], sk[1024];
    int t = threadIdx.x;
    float a = 0.f, bb = 0.f;
    for (int i = t; i < BW; i += 1024) { a += g_partial[i]; bb += g_partial[BW + i]; }
    sq[t] = a; sk[t] = bb;
    __syncthreads();
    for (int s = 512; s > 0; s >>= 1) {
        if (t < s) { sq[t] += sq[t + s]; sk[t] += sk[t + s]; }
        __syncthreads();
    }
    if (t == 0) g_scale = 1.0f / (sqrtf(sq[0]) * sqrtf(sk[0]) * fmaxf(tau[0], 0.01f));
}

// ---------------- kernel 4: attention + proj + residual scatter ----------------
#define SMEM_ATTN_FLOATS (96*96 + 3*49*33 + 49*49 + 49*97 + 200)
__global__ void __launch_bounds__(288) kattn(const float* __restrict__ x,
                                             const float* __restrict__ pw, const float* __restrict__ pb,
                                             float* __restrict__ out) {
    extern __shared__ float sm[];
    float* w_s = sm;                  // 9216
    float* q_s = w_s + 96 * 96;       // 49*33
    float* k_s = q_s + 49 * 33;
    float* v_s = k_s + 49 * 33;
    float* p_s = v_s + 49 * 33;       // 49*49
    float* o_s = p_s + 49 * 49;       // 49*97 (+200 pad after, for OOB-safe reads)

    int t = threadIdx.x;
    int bid = blockIdx.x;
    int b = bid >> 6, wi = bid & 63, wh = wi >> 3, ww = wi & 7;

    for (int i = t; i < 96 * 96; i += 288) w_s[i] = pw[i];
    float scale = g_scale;
    const float* qkvb = g_qkv + (size_t)bid * 9 * (NN * Dd);

    for (int hd = 0; hd < 3; hd++) {
        __syncthreads();
        for (int idx = t; idx < NN * Dd; idx += 288) {
            int n = idx >> 5, dd = idx & 31;
            q_s[n * 33 + dd] = qkvb[(0 + hd) * 1568 + idx];
            k_s[n * 33 + dd] = qkvb[(3 + hd) * 1568 + idx];
            v_s[n * 33 + dd] = qkvb[(6 + hd) * 1568 + idx];
        }
        __syncthreads();
        for (int idx = t; idx < NN * NN; idx += 288) {
            int n = idx / 49, m = idx - 49 * n;
            float acc = 0.f;
#pragma unroll
            for (int kk = 0; kk < 32; kk++) acc += q_s[n * 33 + kk] * k_s[m * 33 + kk];
            int gnh = wh * 7 + n / 7, gnw = ww * 7 + n % 7;
            int gmh = wh * 7 + m / 7, gmw = ww * 7 + m % 7;
            int rn = (gnh < 49 ? 0 : (gnh < 53 ? 1 : 2)) * 3 + (gnw < 49 ? 0 : (gnw < 53 ? 1 : 2));
            int rm = (gmh < 49 ? 0 : (gmh < 53 ? 1 : 2)) * 3 + (gmw < 49 ? 0 : (gmw < 53 ? 1 : 2));
            float mv = (rn == rm) ? 0.f : -100.f;
            p_s[idx] = acc * scale + g_bias[hd * 2401 + idx] + mv;
        }
        __syncthreads();
        if (t < 49) {
            float mx = -1e30f;
            for (int m = 0; m < 49; m++) mx = fmaxf(mx, p_s[t * 49 + m]);
            float s = 0.f;
            for (int m = 0; m < 49; m++) { float e = __expf(p_s[t * 49 + m] - mx); p_s[t * 49 + m] = e; s += e; }
            float inv = 1.f / s;
            for (int m = 0; m < 49; m++) p_s[t * 49 + m] *= inv;
        }
        __syncthreads();
        for (int idx = t; idx < NN * Dd; idx += 288) {
            int n = idx >> 5, dd = idx & 31;
            float acc = 0.f;
            for (int m = 0; m < 49; m++) acc += p_s[n * 49 + m] * v_s[m * 33 + dd];
            o_s[n * 97 + hd * 32 + dd] = acc;
        }
    }
    __syncthreads();

    // proj (96x96) + shortcut, scatter back through inverse shift map
    int c = t % 96, rg = t / 96;
    int base = rg * 17;                // rows base..base+16 (last group has 2 garbage rows, reads padded)
    float acc[17];
#pragma unroll
    for (int r = 0; r < 17; r++) acc[r] = 0.f;
    for (int k = 0; k < 96; k++) {
        float w = w_s[k * 96 + c];
#pragma unroll
        for (int r = 0; r < 17; r++) acc[r] += o_s[(base + r) * 97 + k] * w;
    }
    float pbv = pb[c];
#pragma unroll
    for (int r = 0; r < 17; r++) {
        int n = base + r;
        if (n < 49) {
            int i = n / 7, j = n - 7 * i;
            int hs = wh * 7 + i + 3; if (hs >= 56) hs -= 56;
            int ws = ww * 7 + j + 3; if (ws >= 56) ws -= 56;
            size_t gi = ((size_t)b * 3136 + hs * 56 + ws) * 96 + c;
            out[gi] = x[gi] + acc[r] + pbv;
        }
    }
}

// ---------------- kernel 5: LN + MLP + residual (in-place on out) ----------------
__global__ void __launch_bounds__(384) kmlp(const float* __restrict__ n2g, const float* __restrict__ n2b,
                                            const float* __restrict__ w1, const float* __restrict__ b1,
                                            const float* __restrict__ w2, const float* __restrict__ b2,
                                            float* __restrict__ out) {
    __shared__ float t_s[16 * 97];
    __shared__ float a_s[16 * 388];
    int t = threadIdx.x;
    size_t tok0 = (size_t)blockIdx.x * 16;
    int wid = t >> 5, lane = t & 31;

    // phase 1: LayerNorm of 16 tokens (warp per token)
    for (int tk = wid; tk < 16; tk += 12) {
        const float* row = out + (tok0 + tk) * 96;
        float v0 = row[lane], v1 = row[lane + 32], v2 = row[lane + 64];
        float s = v0 + v1 + v2;
        float ss = v0 * v0 + v1 * v1 + v2 * v2;
        for (int off = 16; off; off >>= 1) {
            s  += __shfl_down_sync(0xffffffffu, s, off);
            ss += __shfl_down_sync(0xffffffffu, ss, off);
        }
        s = __shfl_sync(0xffffffffu, s, 0);
        ss = __shfl_sync(0xffffffffu, ss, 0);
        float mu = s * (1.f / 96.f);
        float rstd = rsqrtf(ss * (1.f / 96.f) - mu * mu + 1e-5f);
        t_s[tk * 97 + lane]      = (v0 - mu) * rstd * n2g[lane]      + n2b[lane];
        t_s[tk * 97 + lane + 32] = (v1 - mu) * rstd * n2g[lane + 32] + n2b[lane + 32];
        t_s[tk * 97 + lane + 64] = (v2 - mu) * rstd * n2g[lane + 64] + n2b[lane + 64];
    }
    __syncthreads();

    // phase 2: fc1 (96 -> 384) + gelu; thread t owns output column t
    {
        float acc[16];
#pragma unroll
        for (int r = 0; r < 16; r++) acc[r] = 0.f;
        for (int k = 0; k < 96; k++) {
            float w = w1[k * 384 + t];
#pragma unroll
            for (int r = 0; r < 16; r++) acc[r] += t_s[r * 97 + k] * w;
        }
        float bb = b1[t];
#pragma unroll
        for (int r = 0; r < 16; r++) a_s[r * 388 + t] = gelu_tanh(acc[r] + bb);
    }
    __syncthreads();

    // phase 3: fc2 (384 -> 96) + residual; thread t -> (col t%96, row group t/96)
    {
        int c = t % 96, rg = t / 96;
        float acc[4] = {0.f, 0.f, 0.f, 0.f};
        const float* ab = a_s + rg * 4 * 388;
        for (int k = 0; k < 384; k++) {
            float w = w2[k * 96 + c];
#pragma unroll
            for (int r = 0; r < 4; r++) acc[r] += ab[r * 388 + k] * w;
        }
        float bb = b2[c];
#pragma unroll
        for (int r = 0; r < 4; r++) {
            size_t gi = (tok0 + rg * 4 + r) * 96 + c;
            out[gi] = out[gi] + acc[r] + bb;
        }
    }
}

// ---------------- launch ----------------
extern "C" void kernel_launch(void* const* d_in, const int* in_sizes, int n_in,
                              void* d_out, int out_size) {
    const float* x   = (const float*)d_in[0];
    const float* n1g = (const float*)d_in[1];
    const float* n1b = (const float*)d_in[2];
    const float* qw  = (const float*)d_in[3];
    const float* qb  = (const float*)d_in[4];
    const float* pw  = (const float*)d_in[5];
    const float* pb  = (const float*)d_in[6];
    const float* mw1 = (const float*)d_in[7];
    const float* mb1 = (const float*)d_in[8];
    const float* mw2 = (const float*)d_in[9];
    const float* mb2 = (const float*)d_in[10];
    const float* tau = (const float*)d_in[11];
    const float* n2g = (const float*)d_in[12];
    const float* n2b = (const float*)d_in[13];
    const float* w1  = (const float*)d_in[14];
    const float* b1  = (const float*)d_in[15];
    const float* w2  = (const float*)d_in[16];
    const float* b2  = (const float*)d_in[17];
    float* out = (float*)d_out;

    const int smem_qkv  = SMEM_QKV_FLOATS * 4;
    const int smem_attn = SMEM_ATTN_FLOATS * 4;
    cudaFuncSetAttribute(kqkv,  cudaFuncAttributeMaxDynamicSharedMemorySize, smem_qkv);
    cudaFuncSetAttribute(kattn, cudaFuncAttributeMaxDynamicSharedMemorySize, smem_attn);

    kprep<<<1, 128>>>(mw1, mb1, mw2, mb2);
    kqkv<<<BW, 288, smem_qkv>>>(x, n1g, n1b, qw, qb);
    kreduce<<<1, 1024>>>(tau);
    kattn<<<BW, 288, smem_attn>>>(x, pw, pb, out);
    kmlp<<<TOKENS / 16, 384>>>(n2g, n2b, w1, b1, w2, b2, out);
}

// round 2
// speedup vs baseline: 1.5943x; 1.5943x over previous
#include <cuda_runtime.h>
#include <math.h>

// ---------------- problem constants ----------------
#define Bn      64
#define Hh      56
#define Wd      56
#define Cc      96
#define NHEADS  3
#define WIN     7
#define NN      49
#define NWn     64
#define BW      (Bn*NWn)      // 4096 windows
#define Dd      32
#define HID     384
#define TOKENS  (Bn*Hh*Wd)    // 200704

// ---------------- device scratch ----------------
__device__ float g_qkv[(size_t)BW * 9 * NN * Dd];   // [win][which3][head3][n][d]
__device__ float g_partial[2 * BW];
__device__ float g_bias[NHEADS * NN * NN];
__device__ float g_scale;

// ---------------- f32x2 packed math helpers ----------------
typedef unsigned long long ull;
__device__ __forceinline__ ull pk2(float a, float b) {
    ull r; asm("mov.b64 %0, {%1,%2};" : "=l"(r) : "f"(a), "f"(b)); return r;
}
__device__ __forceinline__ void fma2(ull& d, ull a, ull b) {
    asm("fma.rn.f32x2 %0, %1, %2, %3;" : "=l"(d) : "l"(a), "l"(b), "l"(d));
}
__device__ __forceinline__ void upk2(ull v, float& a, float& b) {
    asm("mov.b64 {%0,%1}, %2;" : "=f"(a), "=f"(b) : "l"(v));
}

__device__ __forceinline__ float gelu_tanh(float x) {
    float u = 0.7978845608028654f * (x + 0.044715f * x * x * x);
    float e = __expf(2.f * u);
    float t = 1.f - 2.f * __frcp_rn(e + 1.f);
    return 0.5f * x * (1.f + t);
}

// ---------------- kernel 1: CPB bias table ----------------
__global__ void kprep(const float* __restrict__ w1, const float* __restrict__ b1,
                      const float* __restrict__ w2, const float* __restrict__ b2) {
    int t = threadIdx.x;
    for (int idx = t; idx < NN * NN; idx += blockDim.x) {
        int n = idx / NN, m = idx - NN * n;
        float di = (float)(n / WIN - m / WIN);
        float dj = (float)(n % WIN - m % WIN);
        float fdi = (di > 0.f ? 1.f : (di < 0.f ? -1.f : 0.f)) * log1pf(fabsf(di));
        float fdj = (dj > 0.f ? 1.f : (dj < 0.f ? -1.f : 0.f)) * log1pf(fabsf(dj));
        float a0 = 0.f, a1 = 0.f, a2 = 0.f;
        for (int h = 0; h < 128; h++) {
            float v = fdi * w1[h] + fdj * w1[128 + h] + b1[h];
            float x3 = v * v * v;
            float g = 0.5f * v * (1.0f + tanhf(0.7978845608028654f * (v + 0.044715f * x3)));
            a0 += g * w2[h * 3 + 0];
            a1 += g * w2[h * 3 + 1];
            a2 += g * w2[h * 3 + 2];
        }
        g_bias[0 * 2401 + idx] = a0 + b2[0];
        g_bias[1 * 2401 + idx] = a1 + b2[1];
        g_bias[2 * 2401 + idx] = a2 + b2[2];
    }
}

// ---------------- kernel 2: LN + gather + QKV GEMM + sumsq ----------------
// block = 256 threads, one window. 252 active in GEMM: 36 colgroups(8) x 7 rowgroups(7)
__global__ void __launch_bounds__(256, 2) kqkv(const float* __restrict__ x,
                                               const float* __restrict__ n1g, const float* __restrict__ n1b,
                                               const float* __restrict__ qw,  const float* __restrict__ qb) {
    __shared__ float h_s[49 * 97];
    __shared__ float hT[96 * 52];
    __shared__ float mu_s[49], rs_s[49];
    __shared__ float redq[8], redk[8];

    int t = threadIdx.x;
    int bid = blockIdx.x;
    int b = bid >> 6, wi = bid & 63, wh = wi >> 3, ww = wi & 7;

    // gather window tokens through cyclic shift
    for (int idx = t; idx < NN * Cc; idx += 256) {
        int n = idx / 96, c = idx - 96 * n;
        int i = n / 7, j = n - 7 * i;
        int hs = wh * 7 + i + 3; if (hs >= 56) hs -= 56;
        int ws = ww * 7 + j + 3; if (ws >= 56) ws -= 56;
        h_s[n * 97 + c] = x[((size_t)b * 3136 + hs * 56 + ws) * 96 + c];
    }
    __syncthreads();
    // LN stats: warp per token
    {
        int wid = t >> 5, lane = t & 31;
        for (int n = wid; n < 49; n += 8) {
            float v0 = h_s[n * 97 + lane], v1 = h_s[n * 97 + lane + 32], v2 = h_s[n * 97 + lane + 64];
            float s = v0 + v1 + v2, ss = v0 * v0 + v1 * v1 + v2 * v2;
#pragma unroll
            for (int off = 16; off; off >>= 1) {
                s  += __shfl_down_sync(0xffffffffu, s, off);
                ss += __shfl_down_sync(0xffffffffu, ss, off);
            }
            if (lane == 0) {
                float mu = s * (1.f / 96.f);
                mu_s[n] = mu;
                rs_s[n] = rsqrtf(ss * (1.f / 96.f) - mu * mu + 1e-5f);
            }
        }
    }
    __syncthreads();
    // normalized transpose: hT[c][n]
    for (int idx = t; idx < NN * Cc; idx += 256) {
        int n = idx / 96, c = idx - 96 * n;
        hT[c * 52 + n] = (h_s[n * 97 + c] - mu_s[n]) * rs_s[n] * n1g[c] + n1b[c];
    }
    __syncthreads();

    float sqq = 0.f, sqk = 0.f;
    if (t < 252) {
        int cg = t % 36, rg = t / 36;
        int c0 = cg * 8, n0 = rg * 7;
        ull acc2[7][4];
#pragma unroll
        for (int r = 0; r < 7; r++)
#pragma unroll
            for (int j = 0; j < 4; j++) acc2[r][j] = 0ull;

        for (int k = 0; k < 96; k++) {
            const ulonglong2* wp = reinterpret_cast<const ulonglong2*>(qw + k * 288 + c0);
            ulonglong2 wa = wp[0], wb = wp[1];
            ull w4[4] = {wa.x, wa.y, wb.x, wb.y};
            const float* hrow = hT + k * 52 + n0;
            ull hp[7];
#pragma unroll
            for (int r = 0; r < 7; r++) { float hv = hrow[r]; hp[r] = pk2(hv, hv); }
#pragma unroll
            for (int r = 0; r < 7; r++)
#pragma unroll
                for (int j = 0; j < 4; j++) fma2(acc2[r][j], hp[r], w4[j]);
        }
        // epilogue
        int which = c0 / 96;
        int cc = c0 - 96 * which;
        int head = cc >> 5, d0 = cc & 31;
        float bv[8];
#pragma unroll
        for (int j = 0; j < 8; j++) bv[j] = qb[c0 + j];
        float* outp = g_qkv + ((size_t)bid * 9 + which * 3 + head) * 1568 + d0;
#pragma unroll
        for (int r = 0; r < 7; r++) {
            int n = n0 + r;
            float v8[8];
#pragma unroll
            for (int j = 0; j < 4; j++) upk2(acc2[r][j], v8[2 * j], v8[2 * j + 1]);
#pragma unroll
            for (int j = 0; j < 8; j++) v8[j] += bv[j];
            float4* dst = reinterpret_cast<float4*>(outp + n * 32);
            dst[0] = make_float4(v8[0], v8[1], v8[2], v8[3]);
            dst[1] = make_float4(v8[4], v8[5], v8[6], v8[7]);
            if (which == 0) {
#pragma unroll
                for (int j = 0; j < 8; j++) sqq += v8[j] * v8[j];
            } else if (which == 1) {
#pragma unroll
                for (int j = 0; j < 8; j++) sqk += v8[j] * v8[j];
            }
        }
    }
    // deterministic reduction
#pragma unroll
    for (int off = 16; off; off >>= 1) {
        sqq += __shfl_down_sync(0xffffffffu, sqq, off);
        sqk += __shfl_down_sync(0xffffffffu, sqk, off);
    }
    int wid = t >> 5, lane = t & 31;
    if (lane == 0) { redq[wid] = sqq; redk[wid] = sqk; }
    __syncthreads();
    if (t == 0) {
        float a = 0.f, bb = 0.f;
        for (int i = 0; i < 8; i++) { a += redq[i]; bb += redk[i]; }
        g_partial[bid] = a; g_partial[BW + bid] = bb;
    }
}

// ---------------- kernel 3: global reduce -> scale ----------------
__global__ void kreduce(const float* __restrict__ tau) {
    __shared__ float sq[1024], sk[1024];
    int t = threadIdx.x;
    float a = 0.f, bb = 0.f;
    for (int i = t; i < BW; i += 1024) { a += g_partial[i]; bb += g_partial[BW + i]; }
    sq[t] = a; sk[t] = bb;
    __syncthreads();
    for (int s = 512; s > 0; s >>= 1) {
        if (t < s) { sq[t] += sq[t + s]; sk[t] += sk[t + s]; }
        __syncthreads();
    }
    if (t == 0) g_scale = 1.0f / (sqrtf(sq[0]) * sqrtf(sk[0]) * fmaxf(tau[0], 0.01f));
}

// ---------------- kernel 4: attention (3 heads concurrent) + proj + residual ----------------
// block = 192 threads per window.
#define SM_Q   0
#define SM_K   (3*1617)
#define SM_V   (6*1617)
#define SM_P   (9*1617)          // 3 * 49*50
#define SM_O   (SM_P + 3*2450)   // 49*97
#define SMEM_ATTN_FLOATS (SM_O + 49*97)
__global__ void __launch_bounds__(192, 2) kattn(const float* __restrict__ x,
                                                const float* __restrict__ pw, const float* __restrict__ pb,
                                                float* __restrict__ out) {
    extern __shared__ float sm[];
    int t = threadIdx.x;
    int bid = blockIdx.x;
    int b = bid >> 6, wi = bid & 63, wh = wi >> 3, ww = wi & 7;

    const float* qkvb = g_qkv + (size_t)bid * 9 * 1568;
    // load q,k,v (3 heads each) into padded smem [h][n*33+d]
    for (int i = t; i < 3 * 1568; i += 192) {
        int h = i / 1568, r = i - 1568 * h;
        int n = r >> 5, d = r & 31;
        sm[SM_Q + h * 1617 + n * 33 + d] = qkvb[h * 1568 + r];
        sm[SM_K + h * 1617 + n * 33 + d] = qkvb[(3 + h) * 1568 + r];
        sm[SM_V + h * 1617 + n * 33 + d] = qkvb[(6 + h) * 1568 + r];
    }
    __syncthreads();

    float scale = g_scale;
    // QK^T: 147 threads: (head, 7x7 tile)
    if (t < 147) {
        int h = t / 49, tile = t - 49 * h;
        int tn = tile / 7, tm = tile - 7 * tn;
        int n0 = tn * 7, m0 = tm * 7;
        const float* qs = sm + SM_Q + h * 1617;
        const float* ks = sm + SM_K + h * 1617;
        ull acc2[7][4];
#pragma unroll
        for (int r = 0; r < 7; r++)
#pragma unroll
            for (int j = 0; j < 4; j++) acc2[r][j] = 0ull;
        for (int kk = 0; kk < 32; kk++) {
            float qv[7], kv[7];
#pragma unroll
            for (int r = 0; r < 7; r++) qv[r] = qs[(n0 + r) * 33 + kk];
#pragma unroll
            for (int j = 0; j < 7; j++) kv[j] = ks[(m0 + j) * 33 + kk];
            ull kp[4] = {pk2(kv[0], kv[1]), pk2(kv[2], kv[3]), pk2(kv[4], kv[5]), pk2(kv[6], kv[6])};
#pragma unroll
            for (int r = 0; r < 7; r++) {
                ull qp = pk2(qv[r], qv[r]);
#pragma unroll
                for (int j = 0; j < 4; j++) fma2(acc2[r][j], qp, kp[j]);
            }
        }
        // regions: tile rows share image-row tn; cols share image-row tm
        int gnh = wh * 7 + tn, gmh = wh * 7 + tm;
        int rhn = (gnh < 49 ? 0 : (gnh < 53 ? 1 : 2));
        int rhm = (gmh < 49 ? 0 : (gmh < 53 ? 1 : 2));
        int rn[7], rm[7];
#pragma unroll
        for (int r = 0; r < 7; r++) {
            int gw = ww * 7 + r;
            int rw = (gw < 49 ? 0 : (gw < 53 ? 1 : 2));
            rn[r] = rhn * 3 + rw;
            rm[r] = rhm * 3 + rw;
        }
        float* ps = sm + SM_P + h * 2450;
        const float* bs = g_bias + h * 2401;
#pragma unroll
        for (int r = 0; r < 7; r++) {
            int n = n0 + r;
            float v8[8];
#pragma unroll
            for (int j = 0; j < 4; j++) upk2(acc2[r][j], v8[2 * j], v8[2 * j + 1]);
#pragma unroll
            for (int j = 0; j < 7; j++) {
                int m = m0 + j;
                float mv = (rn[r] == rm[j]) ? 0.f : -100.f;
                ps[n * 50 + m] = v8[j] * scale + bs[n * 49 + m] + mv;
            }
        }
    }
    __syncthreads();
    // softmax: 147 threads: (head, row)
    if (t < 147) {
        int h = t / 49, n = t - 49 * h;
        float* row = sm + SM_P + h * 2450 + n * 50;
        float mx = -1e30f;
        for (int m = 0; m < 49; m++) mx = fmaxf(mx, row[m]);
        float s = 0.f;
        for (int m = 0; m < 49; m++) { float e = __expf(row[m] - mx); row[m] = e; s += e; }
        float inv = __frcp_rn(s);
        for (int m = 0; m < 49; m++) row[m] *= inv;
    }
    __syncthreads();
    // PV: 168 threads: (head, 7 rows x 4 cols)
    if (t < 168) {
        int h = t / 56, r2 = t - 56 * h;
        int rg = r2 / 8, cg = r2 - 8 * rg;
        int n0 = rg * 7, d0 = cg * 4;
        const float* ps = sm + SM_P + h * 2450;
        const float* vs = sm + SM_V + h * 1617;
        ull acc2[7][2];
#pragma unroll
        for (int r = 0; r < 7; r++) { acc2[r][0] = 0ull; acc2[r][1] = 0ull; }
        for (int m = 0; m < 49; m++) {
            float vv0 = vs[m * 33 + d0], vv1 = vs[m * 33 + d0 + 1];
            float vv2 = vs[m * 33 + d0 + 2], vv3 = vs[m * 33 + d0 + 3];
            ull vp0 = pk2(vv0, vv1), vp1 = pk2(vv2, vv3);
#pragma unroll
            for (int r = 0; r < 7; r++) {
                float pv = ps[(n0 + r) * 50 + m];
                ull pp = pk2(pv, pv);
                fma2(acc2[r][0], pp, vp0);
                fma2(acc2[r][1], pp, vp1);
            }
        }
        float* os = sm + SM_O;
#pragma unroll
        for (int r = 0; r < 7; r++) {
            float f0, f1, f2, f3;
            upk2(acc2[r][0], f0, f1); upk2(acc2[r][1], f2, f3);
            float* dst = os + (n0 + r) * 97 + h * 32 + d0;
            dst[0] = f0; dst[1] = f1; dst[2] = f2; dst[3] = f3;
        }
    }
    __syncthreads();
    // proj + residual scatter: 168 threads: (7 rows x 4 cols), rows n0=rg*7
    if (t < 168) {
        int rg = t / 24, cg = t - 24 * rg;
        int n0 = rg * 7, c0 = cg * 4;
        const float* os = sm + SM_O;
        ull acc2[7][2];
#pragma unroll
        for (int r = 0; r < 7; r++) { acc2[r][0] = 0ull; acc2[r][1] = 0ull; }
        for (int k = 0; k < 96; k++) {
            ulonglong2 wv = *reinterpret_cast<const ulonglong2*>(pw + k * 96 + c0);
#pragma unroll
            for (int r = 0; r < 7; r++) {
                float ov = os[(n0 + r) * 97 + k];
                ull op = pk2(ov, ov);
                fma2(acc2[r][0], op, wv.x);
                fma2(acc2[r][1], op, wv.y);
            }
        }
        float pb0 = pb[c0], pb1 = pb[c0 + 1], pb2 = pb[c0 + 2], pb3 = pb[c0 + 3];
        // rows n0..n0+6 -> window coords i=rg, j=r
        int hs = wh * 7 + rg + 3; if (hs >= 56) hs -= 56;
#pragma unroll
        for (int r = 0; r < 7; r++) {
            int ws = ww * 7 + r + 3; if (ws >= 56) ws -= 56;
            size_t gi = ((size_t)b * 3136 + hs * 56 + ws) * 96 + c0;
            float f0, f1, f2, f3;
            upk2(acc2[r][0], f0, f1); upk2(acc2[r][1], f2, f3);
            float4 xr = *reinterpret_cast<const float4*>(x + gi);
            float4 o4 = make_float4(xr.x + f0 + pb0, xr.y + f1 + pb1,
                                    xr.z + f2 + pb2, xr.w + f3 + pb3);
            *reinterpret_cast<float4*>(out + gi) = o4;
        }
    }
}

// ---------------- kernel 5: LN + MLP + residual (in-place on out) ----------------
// block = 192 threads, 32 tokens.
#define SM_TT  0                 // tT[96][33]
#define SM_AT  (96*33)           // aT[384][33]
#define SMEM_MLP_FLOATS (SM_AT + 384*33)
__global__ void __launch_bounds__(192, 2) kmlp(const float* __restrict__ n2g, const float* __restrict__ n2b,
                                               const float* __restrict__ w1, const float* __restrict__ b1,
                                               const float* __restrict__ w2, const float* __restrict__ b2,
                                               float* __restrict__ out) {
    extern __shared__ float sm[];
    float* tT = sm + SM_TT;
    float* aT = sm + SM_AT;
    int t = threadIdx.x;
    size_t tok0 = (size_t)blockIdx.x * 32;
    int wid = t >> 5, lane = t & 31;

    // LN: warp per token, write transposed
    for (int n = wid; n < 32; n += 6) {
        const float* row = out + (tok0 + n) * 96;
        float v0 = row[lane], v1 = row[lane + 32], v2 = row[lane + 64];
        float s = v0 + v1 + v2, ss = v0 * v0 + v1 * v1 + v2 * v2;
#pragma unroll
        for (int off = 16; off; off >>= 1) {
            s  += __shfl_down_sync(0xffffffffu, s, off);
            ss += __shfl_down_sync(0xffffffffu, ss, off);
        }
        s = __shfl_sync(0xffffffffu, s, 0);
        ss = __shfl_sync(0xffffffffu, ss, 0);
        float mu = s * (1.f / 96.f);
        float rstd = rsqrtf(ss * (1.f / 96.f) - mu * mu + 1e-5f);
        tT[lane * 33 + n]        = (v0 - mu) * rstd * n2g[lane]      + n2b[lane];
        tT[(lane + 32) * 33 + n] = (v1 - mu) * rstd * n2g[lane + 32] + n2b[lane + 32];
        tT[(lane + 64) * 33 + n] = (v2 - mu) * rstd * n2g[lane + 64] + n2b[lane + 64];
    }
    __syncthreads();

    // fc1: 192 threads = 4 rowgroups(8 tok) x 48 colgroups(8 cols)
    {
        int rg = t / 48, cg = t - 48 * rg;
        int r0 = rg * 8, c0 = cg * 8;
        ull acc2[8][4];
#pragma unroll
        for (int r = 0; r < 8; r++)
#pragma unroll
            for (int j = 0; j < 4; j++) acc2[r][j] = 0ull;
        for (int k = 0; k < 96; k++) {
            const ulonglong2* wp = reinterpret_cast<const ulonglong2*>(w1 + k * 384 + c0);
            ulonglong2 wa = wp[0], wb = wp[1];
            ull w4[4] = {wa.x, wa.y, wb.x, wb.y};
            const float* trow = tT + k * 33 + r0;
#pragma unroll
            for (int r = 0; r < 8; r++) {
                float tv = trow[r];
                ull tp = pk2(tv, tv);
#pragma unroll
                for (int j = 0; j < 4; j++) fma2(acc2[r][j], tp, w4[j]);
            }
        }
        float bv[8];
#pragma unroll
        for (int j = 0; j < 8; j++) bv[j] = b1[c0 + j];
#pragma unroll
        for (int r = 0; r < 8; r++) {
            float v8[8];
#pragma unroll
            for (int j = 0; j < 4; j++) upk2(acc2[r][j], v8[2 * j], v8[2 * j + 1]);
#pragma unroll
            for (int j = 0; j < 8; j++)
                aT[(c0 + j) * 33 + r0 + r] = gelu_tanh(v8[j] + bv[j]);
        }
    }
    __syncthreads();

    // fc2: 192 threads = 16 rowgroups(2 tok) x 12 colgroups(8 cols)
    {
        int rg = t / 12, cg = t - 12 * rg;
        int r0 = rg * 2, c0 = cg * 8;
        ull acc2[2][4];
#pragma unroll
        for (int r = 0; r < 2; r++)
#pragma unroll
            for (int j = 0; j < 4; j++) acc2[r][j] = 0ull;
        for (int k = 0; k < 384; k++) {
            const ulonglong2* wp = reinterpret_cast<const ulonglong2*>(w2 + k * 96 + c0);
            ulonglong2 wa = wp[0], wb = wp[1];
            ull w4[4] = {wa.x, wa.y, wb.x, wb.y};
            float t0 = aT[k * 33 + r0], t1 = aT[k * 33 + r0 + 1];
            ull tp0 = pk2(t0, t0), tp1 = pk2(t1, t1);
#pragma unroll
            for (int j = 0; j < 4; j++) { fma2(acc2[0][j], tp0, w4[j]); fma2(acc2[1][j], tp1, w4[j]); }
        }
        float bv[8];
#pragma unroll
        for (int j = 0; j < 8; j++) bv[j] = b2[c0 + j];
#pragma unroll
        for (int r = 0; r < 2; r++) {
            float v8[8];
#pragma unroll
            for (int j = 0; j < 4; j++) upk2(acc2[r][j], v8[2 * j], v8[2 * j + 1]);
            size_t gi = (tok0 + r0 + r) * 96 + c0;
            float4 o0 = *reinterpret_cast<float4*>(out + gi);
            float4 o1 = *reinterpret_cast<float4*>(out + gi + 4);
            o0.x += v8[0] + bv[0]; o0.y += v8[1] + bv[1]; o0.z += v8[2] + bv[2]; o0.w += v8[3] + bv[3];
            o1.x += v8[4] + bv[4]; o1.y += v8[5] + bv[5]; o1.z += v8[6] + bv[6]; o1.w += v8[7] + bv[7];
            *reinterpret_cast<float4*>(out + gi) = o0;
            *reinterpret_cast<float4*>(out + gi + 4) = o1;
        }
    }
}

// ---------------- launch ----------------
extern "C" void kernel_launch(void* const* d_in, const int* in_sizes, int n_in,
                              void* d_out, int out_size) {
    const float* x   = (const float*)d_in[0];
    const float* n1g = (const float*)d_in[1];
    const float* n1b = (const float*)d_in[2];
    const float* qw  = (const float*)d_in[3];
    const float* qb  = (const float*)d_in[4];
    const float* pw  = (const float*)d_in[5];
    const float* pb  = (const float*)d_in[6];
    const float* mw1 = (const float*)d_in[7];
    const float* mb1 = (const float*)d_in[8];
    const float* mw2 = (const float*)d_in[9];
    const float* mb2 = (const float*)d_in[10];
    const float* tau = (const float*)d_in[11];
    const float* n2g = (const float*)d_in[12];
    const float* n2b = (const float*)d_in[13];
    const float* w1  = (const float*)d_in[14];
    const float* b1  = (const float*)d_in[15];
    const float* w2  = (const float*)d_in[16];
    const float* b2  = (const float*)d_in[17];
    float* out = (float*)d_out;

    const int smem_attn = SMEM_ATTN_FLOATS * 4;
    const int smem_mlp  = SMEM_MLP_FLOATS * 4;
    cudaFuncSetAttribute(kattn, cudaFuncAttributeMaxDynamicSharedMemorySize, smem_attn);
    cudaFuncSetAttribute(kmlp,  cudaFuncAttributeMaxDynamicSharedMemorySize, smem_mlp);

    kprep<<<1, 128>>>(mw1, mb1, mw2, mb2);
    kqkv<<<BW, 256>>>(x, n1g, n1b, qw, qb);
    kreduce<<<1, 1024>>>(tau);
    kattn<<<BW, 192, smem_attn>>>(x, pw, pb, out);
    kmlp<<<TOKENS / 32, 192, smem_mlp>>>(n2g, n2b, w1, b1, w2, b2, out);
}

// round 3
// speedup vs baseline: 1.6122x; 1.0112x over previous
#include <cuda_runtime.h>
#include <math.h>

// ---------------- problem constants ----------------
#define Bn      64
#define Hh      56
#define Wd      56
#define Cc      96
#define NHEADS  3
#define WIN     7
#define NN      49
#define NWn     64
#define BW      (Bn*NWn)      // 4096 windows
#define Dd      32
#define HID     384
#define TOKENS  (Bn*Hh*Wd)    // 200704

// ---------------- device scratch ----------------
__device__ float g_qkv[(size_t)BW * 9 * NN * Dd];   // [win][which3][head3][n][d]
__device__ float g_partial[2 * BW];
__device__ float g_bias[NHEADS * NN * NN];
__device__ float g_scale;

// ---------------- f32x2 packed math helpers ----------------
typedef unsigned long long ull;
__device__ __forceinline__ ull pk2(float a, float b) {
    ull r; asm("mov.b64 %0, {%1,%2};" : "=l"(r) : "f"(a), "f"(b)); return r;
}
__device__ __forceinline__ void fma2(ull& d, ull a, ull b) {
    asm("fma.rn.f32x2 %0, %1, %2, %3;" : "=l"(d) : "l"(a), "l"(b), "l"(d));
}
__device__ __forceinline__ void upk2(ull v, float& a, float& b) {
    asm("mov.b64 {%0,%1}, %2;" : "=f"(a), "=f"(b) : "l"(v));
}

__device__ __forceinline__ float gelu_tanh(float x) {
    float u = 0.7978845608028654f * (x + 0.044715f * x * x * x);
    float e = __expf(2.f * u);
    float t = 1.f - 2.f * __frcp_rn(e + 1.f);
    return 0.5f * x * (1.f + t);
}

// ---------------- kernel 1: CPB bias table (parallel over 19 blocks) ----------------
__global__ void kprep(const float* __restrict__ w1, const float* __restrict__ b1,
                      const float* __restrict__ w2, const float* __restrict__ b2) {
    int t = blockIdx.x * blockDim.x + threadIdx.x;
    int stride = gridDim.x * blockDim.x;
    for (int idx = t; idx < NN * NN; idx += stride) {
        int n = idx / NN, m = idx - NN * n;
        float di = (float)(n / WIN - m / WIN);
        float dj = (float)(n % WIN - m % WIN);
        float fdi = (di > 0.f ? 1.f : (di < 0.f ? -1.f : 0.f)) * log1pf(fabsf(di));
        float fdj = (dj > 0.f ? 1.f : (dj < 0.f ? -1.f : 0.f)) * log1pf(fabsf(dj));
        float a0 = 0.f, a1 = 0.f, a2 = 0.f;
        for (int h = 0; h < 128; h++) {
            float v = fdi * w1[h] + fdj * w1[128 + h] + b1[h];
            float x3 = v * v * v;
            float g = 0.5f * v * (1.0f + tanhf(0.7978845608028654f * (v + 0.044715f * x3)));
            a0 += g * w2[h * 3 + 0];
            a1 += g * w2[h * 3 + 1];
            a2 += g * w2[h * 3 + 2];
        }
        g_bias[0 * 2401 + idx] = a0 + b2[0];
        g_bias[1 * 2401 + idx] = a1 + b2[1];
        g_bias[2 * 2401 + idx] = a2 + b2[2];
    }
}

// ---------------- kernel 2: LN + gather + QKV GEMM + sumsq ----------------
// dynamic smem: h_s[49*97] floats, hTd[96*52] ulls (duplicated normalized activations)
#define QKV_HS_F   (49*97)                    // 4753, pad to 4768 (8B align)
#define QKV_HTD_O  4768
#define QKV_SMEM_F (QKV_HTD_O + 96*52*2)      // 14752 floats
__global__ void __launch_bounds__(256, 2) kqkv(const float* __restrict__ x,
                                               const float* __restrict__ n1g, const float* __restrict__ n1b,
                                               const float* __restrict__ qw,  const float* __restrict__ qb) {
    extern __shared__ float sm[];
    float* h_s = sm;
    ull*  hTd = (ull*)(sm + QKV_HTD_O);
    __shared__ float mu_s[49], rs_s[49];
    __shared__ float redq[8], redk[8];

    int t = threadIdx.x;
    int bid = blockIdx.x;
    int b = bid >> 6, wi = bid & 63, wh = wi >> 3, ww = wi & 7;

    for (int idx = t; idx < NN * Cc; idx += 256) {
        int n = idx / 96, c = idx - 96 * n;
        int i = n / 7, j = n - 7 * i;
        int hs = wh * 7 + i + 3; if (hs >= 56) hs -= 56;
        int ws = ww * 7 + j + 3; if (ws >= 56) ws -= 56;
        h_s[n * 97 + c] = x[((size_t)b * 3136 + hs * 56 + ws) * 96 + c];
    }
    __syncthreads();
    {
        int wid = t >> 5, lane = t & 31;
        for (int n = wid; n < 49; n += 8) {
            float v0 = h_s[n * 97 + lane], v1 = h_s[n * 97 + lane + 32], v2 = h_s[n * 97 + lane + 64];
            float s = v0 + v1 + v2, ss = v0 * v0 + v1 * v1 + v2 * v2;
#pragma unroll
            for (int off = 16; off; off >>= 1) {
                s  += __shfl_down_sync(0xffffffffu, s, off);
                ss += __shfl_down_sync(0xffffffffu, ss, off);
            }
            if (lane == 0) {
                float mu = s * (1.f / 96.f);
                mu_s[n] = mu;
                rs_s[n] = rsqrtf(ss * (1.f / 96.f) - mu * mu + 1e-5f);
            }
        }
    }
    __syncthreads();
    for (int idx = t; idx < NN * Cc; idx += 256) {
        int n = idx / 96, c = idx - 96 * n;
        float v = (h_s[n * 97 + c] - mu_s[n]) * rs_s[n] * n1g[c] + n1b[c];
        hTd[c * 52 + n] = pk2(v, v);
    }
    __syncthreads();

    float sqq = 0.f, sqk = 0.f;
    if (t < 252) {
        int cg = t % 36, rg = t / 36;
        int c0 = cg * 8, n0 = rg * 7;
        ull acc2[7][4];
#pragma unroll
        for (int r = 0; r < 7; r++)
#pragma unroll
            for (int j = 0; j < 4; j++) acc2[r][j] = 0ull;

        for (int k = 0; k < 96; k++) {
            const ulonglong2* wp = reinterpret_cast<const ulonglong2*>(qw + k * 288 + c0);
            ulonglong2 wa = wp[0], wb = wp[1];
            ull w4[4] = {wa.x, wa.y, wb.x, wb.y};
            const ull* hrow = hTd + k * 52 + n0;
            ull hp[7];
#pragma unroll
            for (int r = 0; r < 7; r++) hp[r] = hrow[r];
#pragma unroll
            for (int r = 0; r < 7; r++)
#pragma unroll
                for (int j = 0; j < 4; j++) fma2(acc2[r][j], hp[r], w4[j]);
        }
        int which = c0 / 96;
        int cc = c0 - 96 * which;
        int head = cc >> 5, d0 = cc & 31;
        float bv[8];
#pragma unroll
        for (int j = 0; j < 8; j++) bv[j] = qb[c0 + j];
        float* outp = g_qkv + ((size_t)bid * 9 + which * 3 + head) * 1568 + d0;
#pragma unroll
        for (int r = 0; r < 7; r++) {
            int n = n0 + r;
            float v8[8];
#pragma unroll
            for (int j = 0; j < 4; j++) upk2(acc2[r][j], v8[2 * j], v8[2 * j + 1]);
#pragma unroll
            for (int j = 0; j < 8; j++) v8[j] += bv[j];
            float4* dst = reinterpret_cast<float4*>(outp + n * 32);
            dst[0] = make_float4(v8[0], v8[1], v8[2], v8[3]);
            dst[1] = make_float4(v8[4], v8[5], v8[6], v8[7]);
            if (which == 0) {
#pragma unroll
                for (int j = 0; j < 8; j++) sqq += v8[j] * v8[j];
            } else if (which == 1) {
#pragma unroll
                for (int j = 0; j < 8; j++) sqk += v8[j] * v8[j];
            }
        }
    }
#pragma unroll
    for (int off = 16; off; off >>= 1) {
        sqq += __shfl_down_sync(0xffffffffu, sqq, off);
        sqk += __shfl_down_sync(0xffffffffu, sqk, off);
    }
    int wid = t >> 5, lane = t & 31;
    if (lane == 0) { redq[wid] = sqq; redk[wid] = sqk; }
    __syncthreads();
    if (t == 0) {
        float a = 0.f, bb = 0.f;
        for (int i = 0; i < 8; i++) { a += redq[i]; bb += redk[i]; }
        g_partial[bid] = a; g_partial[BW + bid] = bb;
    }
}

// ---------------- kernel 3: global reduce -> scale ----------------
__global__ void kreduce(const float* __restrict__ tau) {
    __shared__ float sq[1024], sk[1024];
    int t = threadIdx.x;
    float a = 0.f, bb = 0.f;
    for (int i = t; i < BW; i += 1024) { a += g_partial[i]; bb += g_partial[BW + i]; }
    sq[t] = a; sk[t] = bb;
    __syncthreads();
    for (int s = 512; s > 0; s >>= 1) {
        if (t < s) { sq[t] += sq[t + s]; sk[t] += sk[t + s]; }
        __syncthreads();
    }
    if (t == 0) g_scale = 1.0f / (sqrtf(sq[0]) * sqrtf(sk[0]) * fmaxf(tau[0], 0.01f));
}

// ---------------- kernel 4: attention (3 heads concurrent) + proj + residual ----------------
// smem (floats):
//   qd  : dup q,  ull[3*49*33]  @ 0         (9702 f)  -- dead after QK; o_dup overlays here
//   kTp : K pairs ull[3*7*4*33] @ 9702      (5544 f)
//   v   : float [3][49][34]     @ 15246     (4998 f)
//   p   : float [3][49][50]     @ 20244     (7350 f)
#define AT_QD_O   0
#define AT_KTP_O  9702
#define AT_V_O    15246
#define AT_P_O    20244
#define AT_SMEM_F 27594
__global__ void __launch_bounds__(192, 2) kattn(const float* __restrict__ x,
                                                const float* __restrict__ pw, const float* __restrict__ pb,
                                                float* __restrict__ out) {
    extern __shared__ float sm[];
    ull*   qd  = (ull*)(sm + AT_QD_O);
    ull*   kTp = (ull*)(sm + AT_KTP_O);
    float* vsm = sm + AT_V_O;
    float* psm = sm + AT_P_O;
    ull*   od  = (ull*)(sm + AT_QD_O);     // overlay (q dead after QK)

    int t = threadIdx.x;
    int bid = blockIdx.x;
    int b = bid >> 6, wi = bid & 63, wh = wi >> 3, ww = wi & 7;

    const float* qkvb = g_qkv + (size_t)bid * 9 * 1568;

    // load q (dup) and v
    for (int i = t; i < 3 * 1568; i += 192) {
        int d = i & 31, r = i >> 5;
        int n = r % 49, h = r / 49;
        float q = qkvb[i];
        qd[(h * 49 + n) * 33 + d] = pk2(q, q);
        vsm[(h * 49 + n) * 34 + d] = qkvb[2 * 4704 + i];
    }
    // build K pairs: kTp[((h*7+tm)*4+j)*33+kk] = (k[m0+2j], k[m0+min(2j+1,6)])
    for (int i = t; i < 3 * 7 * 4 * 32; i += 192) {
        int kk = i & 31, r = i >> 5;
        int j = r & 3; r >>= 2;
        int tm = r % 7, h = r / 7;
        int m1 = tm * 7 + 2 * j;
        int m2 = tm * 7 + (2 * j + 1 < 7 ? 2 * j + 1 : 6);
        const float* kb = qkvb + (3 + h) * 1568;
        kTp[((h * 7 + tm) * 4 + j) * 33 + kk] = pk2(kb[m1 * 32 + kk], kb[m2 * 32 + kk]);
    }
    __syncthreads();

    float scale = g_scale;
    // QK^T: 147 threads: (head, 7x7 tile)
    if (t < 147) {
        int h = t / 49, tile = t - 49 * h;
        int tn = tile / 7, tm = tile - 7 * tn;
        int n0 = tn * 7;
        const ull* qb_ = qd + (h * 49 + n0) * 33;
        const ull* kb_ = kTp + ((h * 7 + tm) * 4) * 33;
        ull acc2[7][4];
#pragma unroll
        for (int r = 0; r < 7; r++)
#pragma unroll
            for (int j = 0; j < 4; j++) acc2[r][j] = 0ull;
        for (int kk = 0; kk < 32; kk++) {
            ull kp[4];
#pragma unroll
            for (int j = 0; j < 4; j++) kp[j] = kb_[j * 33 + kk];
#pragma unroll
            for (int r = 0; r < 7; r++) {
                ull qp = qb_[r * 33 + kk];
#pragma unroll
                for (int j = 0; j < 4; j++) fma2(acc2[r][j], qp, kp[j]);
            }
        }
        int gnh = wh * 7 + tn, gmh = wh * 7 + tm;
        int rhn = (gnh < 49 ? 0 : (gnh < 53 ? 1 : 2));
        int rhm = (gmh < 49 ? 0 : (gmh < 53 ? 1 : 2));
        int rn[7], rm[7];
#pragma unroll
        for (int r = 0; r < 7; r++) {
            int gw = ww * 7 + r;
            int rw = (gw < 49 ? 0 : (gw < 53 ? 1 : 2));
            rn[r] = rhn * 3 + rw;
            rm[r] = rhm * 3 + rw;
        }
        float* ps = psm + h * 2450;
        const float* bs = g_bias + h * 2401;
        int m0 = tm * 7;
#pragma unroll
        for (int r = 0; r < 7; r++) {
            int n = n0 + r;
            float v8[8];
#pragma unroll
            for (int j = 0; j < 4; j++) upk2(acc2[r][j], v8[2 * j], v8[2 * j + 1]);
#pragma unroll
            for (int j = 0; j < 7; j++) {
                int m = m0 + j;
                float mv = (rn[r] == rm[j]) ? 0.f : -100.f;
                ps[n * 50 + m] = v8[j] * scale + bs[n * 49 + m] + mv;
            }
        }
    }
    __syncthreads();
    // softmax: 147 threads
    if (t < 147) {
        int h = t / 49, n = t - 49 * h;
        float* row = psm + h * 2450 + n * 50;
        float mx = -1e30f;
        for (int m = 0; m < 49; m++) mx = fmaxf(mx, row[m]);
        float s = 0.f;
        for (int m = 0; m < 49; m++) { float e = __expf(row[m] - mx); row[m] = e; s += e; }
        float inv = __frcp_rn(s);
        for (int m = 0; m < 49; m++) row[m] *= inv;
    }
    __syncthreads();
    // PV: 168 threads: (head, 7 rows x 4 cols) -> write o dup (overlay on qd)
    if (t < 168) {
        int h = t / 56, r2 = t - 56 * h;
        int rg = r2 / 8, cg = r2 - 8 * rg;
        int n0 = rg * 7, d0 = cg * 4;
        const float* ps = psm + h * 2450;
        const ull* vp_base = (const ull*)(vsm + h * 49 * 34);   // rows stride 17 ull
        ull acc2[7][2];
#pragma unroll
        for (int r = 0; r < 7; r++) { acc2[r][0] = 0ull; acc2[r][1] = 0ull; }
        for (int m = 0; m < 49; m++) {
            ull vp0 = vp_base[m * 17 + (d0 >> 1)];
            ull vp1 = vp_base[m * 17 + (d0 >> 1) + 1];
#pragma unroll
            for (int r = 0; r < 7; r++) {
                float pv = ps[(n0 + r) * 50 + m];
                ull pp = pk2(pv, pv);
                fma2(acc2[r][0], pp, vp0);
                fma2(acc2[r][1], pp, vp1);
            }
        }
#pragma unroll
        for (int r = 0; r < 7; r++) {
            float f0, f1, f2, f3;
            upk2(acc2[r][0], f0, f1); upk2(acc2[r][1], f2, f3);
            ull* dst = od + (n0 + r) * 97 + h * 32 + d0;
            dst[0] = pk2(f0, f0); dst[1] = pk2(f1, f1);
            dst[2] = pk2(f2, f2); dst[3] = pk2(f3, f3);
        }
    }
    __syncthreads();
    // proj + residual scatter: 168 threads: (7 rows x 4 cols)
    if (t < 168) {
        int rg = t / 24, cg = t - 24 * rg;
        int n0 = rg * 7, c0 = cg * 4;
        ull acc2[7][2];
#pragma unroll
        for (int r = 0; r < 7; r++) { acc2[r][0] = 0ull; acc2[r][1] = 0ull; }
        for (int k = 0; k < 96; k++) {
            ulonglong2 wv = *reinterpret_cast<const ulonglong2*>(pw + k * 96 + c0);
            const ull* orow = od + k;           // column k of o, row stride 97
#pragma unroll
            for (int r = 0; r < 7; r++) {
                ull op = orow[(n0 + r) * 97];
                fma2(acc2[r][0], op, wv.x);
                fma2(acc2[r][1], op, wv.y);
            }
        }
        float pb0 = pb[c0], pb1 = pb[c0 + 1], pb2 = pb[c0 + 2], pb3 = pb[c0 + 3];
        int hs = wh * 7 + rg + 3; if (hs >= 56) hs -= 56;
#pragma unroll
        for (int r = 0; r < 7; r++) {
            int ws = ww * 7 + r + 3; if (ws >= 56) ws -= 56;
            size_t gi = ((size_t)b * 3136 + hs * 56 + ws) * 96 + c0;
            float f0, f1, f2, f3;
            upk2(acc2[r][0], f0, f1); upk2(acc2[r][1], f2, f3);
            float4 xr = *reinterpret_cast<const float4*>(x + gi);
            float4 o4 = make_float4(xr.x + f0 + pb0, xr.y + f1 + pb1,
                                    xr.z + f2 + pb2, xr.w + f3 + pb3);
            *reinterpret_cast<float4*>(out + gi) = o4;
        }
    }
}

// ---------------- kernel 5: LN + MLP + residual (in-place on out) ----------------
// smem: tTd ull[96][34] dup (6528 f), aT float[384][34] (13056 f)
#define MLP_TTD_F (96*34*2)
#define MLP_AT_O  MLP_TTD_F
#define MLP_SMEM_F (MLP_TTD_F + 384*34)
__global__ void __launch_bounds__(192, 2) kmlp(const float* __restrict__ n2g, const float* __restrict__ n2b,
                                               const float* __restrict__ w1, const float* __restrict__ b1,
                                               const float* __restrict__ w2, const float* __restrict__ b2,
                                               float* __restrict__ out) {
    extern __shared__ float sm[];
    ull*   tTd = (ull*)sm;
    float* aT  = sm + MLP_AT_O;
    int t = threadIdx.x;
    size_t tok0 = (size_t)blockIdx.x * 32;
    int wid = t >> 5, lane = t & 31;

    // LN: warp per token, write duplicated transposed
    for (int n = wid; n < 32; n += 6) {
        const float* row = out + (tok0 + n) * 96;
        float v0 = row[lane], v1 = row[lane + 32], v2 = row[lane + 64];
        float s = v0 + v1 + v2, ss = v0 * v0 + v1 * v1 + v2 * v2;
#pragma unroll
        for (int off = 16; off; off >>= 1) {
            s  += __shfl_down_sync(0xffffffffu, s, off);
            ss += __shfl_down_sync(0xffffffffu, ss, off);
        }
        s = __shfl_sync(0xffffffffu, s, 0);
        ss = __shfl_sync(0xffffffffu, ss, 0);
        float mu = s * (1.f / 96.f);
        float rstd = rsqrtf(ss * (1.f / 96.f) - mu * mu + 1e-5f);
        float a0 = (v0 - mu) * rstd * n2g[lane]      + n2b[lane];
        float a1 = (v1 - mu) * rstd * n2g[lane + 32] + n2b[lane + 32];
        float a2 = (v2 - mu) * rstd * n2g[lane + 64] + n2b[lane + 64];
        tTd[lane * 34 + n]        = pk2(a0, a0);
        tTd[(lane + 32) * 34 + n] = pk2(a1, a1);
        tTd[(lane + 64) * 34 + n] = pk2(a2, a2);
    }
    __syncthreads();

    // fc1: 4 rowgroups(8 tok) x 48 colgroups(8 cols)
    {
        int rg = t / 48, cg = t - 48 * rg;
        int r0 = rg * 8, c0 = cg * 8;
        ull acc2[8][4];
#pragma unroll
        for (int r = 0; r < 8; r++)
#pragma unroll
            for (int j = 0; j < 4; j++) acc2[r][j] = 0ull;
        for (int k = 0; k < 96; k++) {
            const ulonglong2* wp = reinterpret_cast<const ulonglong2*>(w1 + k * 384 + c0);
            ulonglong2 wa = wp[0], wb = wp[1];
            ull w4[4] = {wa.x, wa.y, wb.x, wb.y};
            const ulonglong2* trow = reinterpret_cast<const ulonglong2*>(tTd + k * 34 + r0);
            ulonglong2 t01 = trow[0], t23 = trow[1], t45 = trow[2], t67 = trow[3];
            ull tp[8] = {t01.x, t01.y, t23.x, t23.y, t45.x, t45.y, t67.x, t67.y};
#pragma unroll
            for (int r = 0; r < 8; r++)
#pragma unroll
                for (int j = 0; j < 4; j++) fma2(acc2[r][j], tp[r], w4[j]);
        }
        float bv[8];
#pragma unroll
        for (int j = 0; j < 8; j++) bv[j] = b1[c0 + j];
#pragma unroll
        for (int r = 0; r < 8; r++) {
            float v8[8];
#pragma unroll
            for (int j = 0; j < 4; j++) upk2(acc2[r][j], v8[2 * j], v8[2 * j + 1]);
#pragma unroll
            for (int j = 0; j < 8; j++)
                aT[(c0 + j) * 34 + r0 + r] = gelu_tanh(v8[j] + bv[j]);
        }
    }
    __syncthreads();

    // fc2: 16 rowgroups(2 tok) x 12 colgroups(8 cols)
    {
        int rg = t / 12, cg = t - 12 * rg;
        int r0 = rg * 2, c0 = cg * 8;
        ull acc2[2][4];
#pragma unroll
        for (int r = 0; r < 2; r++)
#pragma unroll
            for (int j = 0; j < 4; j++) acc2[r][j] = 0ull;
        for (int k = 0; k < 384; k++) {
            const ulonglong2* wp = reinterpret_cast<const ulonglong2*>(w2 + k * 96 + c0);
            ulonglong2 wa = wp[0], wb = wp[1];
            ull w4[4] = {wa.x, wa.y, wb.x, wb.y};
            float2 a2f = *reinterpret_cast<const float2*>(aT + k * 34 + r0);
            ull tp0 = pk2(a2f.x, a2f.x), tp1 = pk2(a2f.y, a2f.y);
#pragma unroll
            for (int j = 0; j < 4; j++) { fma2(acc2[0][j], tp0, w4[j]); fma2(acc2[1][j], tp1, w4[j]); }
        }
        float bv[8];
#pragma unroll
        for (int j = 0; j < 8; j++) bv[j] = b2[c0 + j];
#pragma unroll
        for (int r = 0; r < 2; r++) {
            float v8[8];
#pragma unroll
            for (int j = 0; j < 4; j++) upk2(acc2[r][j], v8[2 * j], v8[2 * j + 1]);
            size_t gi = (tok0 + r0 + r) * 96 + c0;
            float4 o0 = *reinterpret_cast<float4*>(out + gi);
            float4 o1 = *reinterpret_cast<float4*>(out + gi + 4);
            o0.x += v8[0] + bv[0]; o0.y += v8[1] + bv[1]; o0.z += v8[2] + bv[2]; o0.w += v8[3] + bv[3];
            o1.x += v8[4] + bv[4]; o1.y += v8[5] + bv[5]; o1.z += v8[6] + bv[6]; o1.w += v8[7] + bv[7];
            *reinterpret_cast<float4*>(out + gi) = o0;
            *reinterpret_cast<float4*>(out + gi + 4) = o1;
        }
    }
}

// ---------------- launch ----------------
extern "C" void kernel_launch(void* const* d_in, const int* in_sizes, int n_in,
                              void* d_out, int out_size) {
    const float* x   = (const float*)d_in[0];
    const float* n1g = (const float*)d_in[1];
    const float* n1b = (const float*)d_in[2];
    const float* qw  = (const float*)d_in[3];
    const float* qb  = (const float*)d_in[4];
    const float* pw  = (const float*)d_in[5];
    const float* pb  = (const float*)d_in[6];
    const float* mw1 = (const float*)d_in[7];
    const float* mb1 = (const float*)d_in[8];
    const float* mw2 = (const float*)d_in[9];
    const float* mb2 = (const float*)d_in[10];
    const float* tau = (const float*)d_in[11];
    const float* n2g = (const float*)d_in[12];
    const float* n2b = (const float*)d_in[13];
    const float* w1  = (const float*)d_in[14];
    const float* b1  = (const float*)d_in[15];
    const float* w2  = (const float*)d_in[16];
    const float* b2  = (const float*)d_in[17];
    float* out = (float*)d_out;

    const int smem_qkv  = QKV_SMEM_F * 4;
    const int smem_attn = AT_SMEM_F * 4;
    const int smem_mlp  = MLP_SMEM_F * 4;
    cudaFuncSetAttribute(kqkv,  cudaFuncAttributeMaxDynamicSharedMemorySize, smem_qkv);
    cudaFuncSetAttribute(kattn, cudaFuncAttributeMaxDynamicSharedMemorySize, smem_attn);
    cudaFuncSetAttribute(kmlp,  cudaFuncAttributeMaxDynamicSharedMemorySize, smem_mlp);

    kprep<<<19, 128>>>(mw1, mb1, mw2, mb2);
    kqkv<<<BW, 256, smem_qkv>>>(x, n1g, n1b, qw, qb);
    kreduce<<<1, 1024>>>(tau);
    kattn<<<BW, 192, smem_attn>>>(x, pw, pb, out);
    kmlp<<<TOKENS / 32, 192, smem_mlp>>>(n2g, n2b, w1, b1, w2, b2, out);
}